// round 1
// baseline (speedup 1.0000x reference)
#include <cuda_runtime.h>

#define H 64
#define D 128
#define KCODES 2048

// Scratch (allocation-free rule: __device__ globals)
__device__ float g_wT[H * KCODES];    // w[h][k] = -2*invden[k]*mu_e[k][h], transposed
__device__ float g_A[KCODES];
__device__ float g_invden[KCODES];

// ---------------------------------------------------------------------------
// Kernel 1: preprocess codebook. One warp per code.
// ---------------------------------------------------------------------------
__global__ void prep_codes(const float* __restrict__ emb) {
    int k = blockIdx.x * (blockDim.x >> 5) + (threadIdx.x >> 5);
    int lane = threadIdx.x & 31;
    if (k >= KCODES) return;
    const float* e = emb + (size_t)k * D;
    float m0 = e[lane];
    float m1 = e[lane + 32];
    float l0 = e[64 + lane];
    float l1 = e[96 + lane];
    float me = m0 * m0 + m1 * m1;          // ||mu_e||^2 partial
    float le = 0.5f * (l0 + l1);           // sum(log sigma_e) partial
    float dn = 2.0f * (expf(l0) + expf(l1)); // denominator partial
#pragma unroll
    for (int s = 16; s; s >>= 1) {
        me += __shfl_xor_sync(0xffffffffu, me, s);
        le += __shfl_xor_sync(0xffffffffu, le, s);
        dn += __shfl_xor_sync(0xffffffffu, dn, s);
    }
    float invden = 1.0f / dn;
    if (lane == 0) {
        g_A[k] = le + me * invden;
        g_invden[k] = invden;
    }
    float c = -2.0f * invden;
    g_wT[lane * KCODES + k] = c * m0;
    g_wT[(lane + 32) * KCODES + k] = c * m1;
}

// ---------------------------------------------------------------------------
// Kernel 2: score GEMM + argmin.
// Block: 256 threads (16x16), TM=64 tokens x TN=64 codes per tile, 4x4 microtile.
// Loops 32 code tiles covering K=2048.
// ---------------------------------------------------------------------------
__global__ __launch_bounds__(256, 4) void dist_argmin(const float* __restrict__ x,
                                                      float* __restrict__ idsf) {
    __shared__ float As[64 * 64];   // [h][token]
    __shared__ float Bs[64 * 64];   // [h][code]
    __shared__ float Ssh[64];       // per-token S = ||mu||^2 + sum exp(logvar)
    __shared__ float Part[64 * 4];  // deterministic partial sums for S
    __shared__ float Atile[64];
    __shared__ float IVt[64];

    const int tid = threadIdx.x;
    const int tx = tid & 15;
    const int ty = tid >> 4;
    const int lane = tid & 31;
    const int w = tid >> 5;
    const int tok0 = blockIdx.x * 64;

    // Load x tile (coalesced) + deterministic S reduction.
    // idx = tid + j*256 covers 64 tokens x 128 features; each warp-iteration
    // covers 32 consecutive features of one token -> warp-reduce, store partial.
#pragma unroll 4
    for (int j = 0; j < 32; ++j) {
        int idx = tid + j * 256;
        int t = idx >> 7;       // token within tile
        int c = idx & 127;      // feature
        float v = x[(size_t)(tok0 + t) * D + c];
        float term;
        if (c < 64) {
            As[c * 64 + t] = v; // transposed store for the GEMM
            term = v * v;
        } else {
            term = expf(v);     // sigma_i^2
        }
#pragma unroll
        for (int s = 16; s; s >>= 1)
            term += __shfl_xor_sync(0xffffffffu, term, s);
        if (lane == 0) Part[t * 4 + (w & 3)] = term;
    }
    __syncthreads();
    if (tid < 64)
        Ssh[tid] = Part[tid * 4] + Part[tid * 4 + 1] + Part[tid * 4 + 2] + Part[tid * 4 + 3];

    float bestv[4];
    int besti[4];
#pragma unroll
    for (int i = 0; i < 4; ++i) { bestv[i] = 3.4e38f; besti[i] = 0; }

    for (int kt = 0; kt < KCODES / 64; ++kt) {
        __syncthreads();  // Bs from prev iter fully consumed; Ssh visible on kt=0
        // Load 64x64 code tile as float4 (coalesced along k)
#pragma unroll
        for (int it = 0; it < 4; ++it) {
            int idx4 = tid + it * 256;      // 0..1023
            int h = idx4 >> 4;
            int kc4 = idx4 & 15;
            float4 v = *reinterpret_cast<const float4*>(
                &g_wT[h * KCODES + kt * 64 + kc4 * 4]);
            *reinterpret_cast<float4*>(&Bs[h * 64 + kc4 * 4]) = v;
        }
        if (tid < 64) {
            Atile[tid] = g_A[kt * 64 + tid];
            IVt[tid] = g_invden[kt * 64 + tid];
        }
        __syncthreads();

        float acc[4][4];
#pragma unroll
        for (int i = 0; i < 4; ++i)
#pragma unroll
            for (int j = 0; j < 4; ++j) acc[i][j] = 0.0f;

#pragma unroll 16
        for (int kk = 0; kk < 64; ++kk) {
            float4 a = *reinterpret_cast<const float4*>(&As[kk * 64 + ty * 4]);
            float4 b = *reinterpret_cast<const float4*>(&Bs[kk * 64 + tx * 4]);
            float av[4] = {a.x, a.y, a.z, a.w};
            float bv[4] = {b.x, b.y, b.z, b.w};
#pragma unroll
            for (int i = 0; i < 4; ++i)
#pragma unroll
                for (int j = 0; j < 4; ++j)
                    acc[i][j] = fmaf(av[i], bv[j], acc[i][j]);
        }

        // Bias + running argmin (codes processed in ascending order -> strict <
        // preserves first-occurrence semantics like jnp.argmin)
#pragma unroll
        for (int i = 0; i < 4; ++i) {
            float S = Ssh[ty * 4 + i];
#pragma unroll
            for (int j = 0; j < 4; ++j) {
                int kc = kt * 64 + tx * 4 + j;
                float sc = Atile[tx * 4 + j] + S * IVt[tx * 4 + j] + acc[i][j];
                if (sc < bestv[i]) { bestv[i] = sc; besti[i] = kc; }
            }
        }
    }

    // Reduce argmin across the 16 tx-threads of each token (they occupy a
    // 16-lane-aligned group within one warp: lane = (ty&1)*16 + tx).
#pragma unroll
    for (int i = 0; i < 4; ++i) {
        float v = bestv[i];
        int bi = besti[i];
#pragma unroll
        for (int s = 1; s < 16; s <<= 1) {
            float ov = __shfl_xor_sync(0xffffffffu, v, s);
            int oi = __shfl_xor_sync(0xffffffffu, bi, s);
            if (ov < v || (ov == v && oi < bi)) { v = ov; bi = oi; }
        }
        if (tx == 0) idsf[tok0 + ty * 4 + i] = (float)bi;
    }
}

// ---------------------------------------------------------------------------
// Kernel 3: epilogue. One warp per token.
// out = q[:64] + exp(0.5*q[64:]) * z ;  commitment == codebook == mean((q-x)^2)
// ---------------------------------------------------------------------------
__global__ void epilogue(const float* __restrict__ x, const float* __restrict__ emb,
                         const float* __restrict__ z, const float* __restrict__ idsf,
                         float* __restrict__ out, float* __restrict__ comm,
                         float* __restrict__ cdbk, int ntok) {
    int t = (blockIdx.x * blockDim.x + threadIdx.x) >> 5;
    int lane = threadIdx.x & 31;
    if (t >= ntok) return;
    int id = (int)idsf[t];
    const float* e = emb + (size_t)id * D;
    const float* xr = x + (size_t)t * D;
    float s = 0.0f;
#pragma unroll
    for (int c = lane; c < D; c += 32) {
        float d = e[c] - xr[c];
        s = fmaf(d, d, s);
    }
#pragma unroll
    for (int sh = 16; sh; sh >>= 1) s += __shfl_xor_sync(0xffffffffu, s, sh);
#pragma unroll
    for (int h = lane; h < H; h += 32)
        out[(size_t)t * H + h] = e[h] + expf(0.5f * e[64 + h]) * z[(size_t)t * H + h];
    if (lane == 0) {
        float m = s * (1.0f / D);
        comm[t] = m;
        cdbk[t] = m;
    }
}

// ---------------------------------------------------------------------------
extern "C" void kernel_launch(void* const* d_in, const int* in_sizes, int n_in,
                              void* d_out, int out_size) {
    // Identify inputs by element count for robustness:
    //   x: B*T*D (largest), emb_w: K*D = 262144, z: B*T*H
    const float* x = nullptr;
    const float* emb = nullptr;
    const float* z = nullptr;
    int x_elems = 0;
    // find emb (K*D)
    int emb_idx = -1;
    for (int i = 0; i < n_in; ++i)
        if (in_sizes[i] == KCODES * D) { emb_idx = i; break; }
    if (emb_idx < 0) emb_idx = 1;  // fallback to declared order
    emb = (const float*)d_in[emb_idx];
    // of the remaining, larger = x, smaller = z
    int a = -1, b = -1;
    for (int i = 0; i < n_in; ++i) {
        if (i == emb_idx) continue;
        if (a < 0) a = i; else b = i;
    }
    if (in_sizes[a] >= in_sizes[b]) {
        x = (const float*)d_in[a]; x_elems = in_sizes[a];
        z = (const float*)d_in[b];
    } else {
        x = (const float*)d_in[b]; x_elems = in_sizes[b];
        z = (const float*)d_in[a];
    }

    int ntok = x_elems / D;  // B*T = 32768

    float* o = (float*)d_out;
    float* outp = o;                          // (ntok, H)
    float* idsf = o + (size_t)ntok * H;       // (ntok,)
    float* comm = idsf + ntok;                // (ntok,)
    float* cdbk = comm + ntok;                // (ntok,)

    prep_codes<<<KCODES / 4, 128>>>(emb);
    dist_argmin<<<ntok / 64, 256>>>(x, idsf);
    epilogue<<<ntok / 8, 256>>>(x, emb, z, idsf, outp, comm, cdbk, ntok);
}

// round 2
// speedup vs baseline: 1.1944x; 1.1944x over previous
#include <cuda_runtime.h>

#define H 64
#define D 128
#define KCODES 2048
#define NTOK_TILE 128
#define KTILE 128   // codes per tile

// Scratch (allocation-free rule: __device__ globals)
__device__ float g_wT[H * KCODES];    // w[h][k] = -2*invden[k]*mu_e[k][h], transposed
__device__ float g_A[KCODES];
__device__ float g_invden[KCODES];

// ---------------------------------------------------------------------------
// Kernel 1: preprocess codebook. One warp per code.
// ---------------------------------------------------------------------------
__global__ void prep_codes(const float* __restrict__ emb) {
    int k = blockIdx.x * (blockDim.x >> 5) + (threadIdx.x >> 5);
    int lane = threadIdx.x & 31;
    if (k >= KCODES) return;
    const float* e = emb + (size_t)k * D;
    float m0 = e[lane];
    float m1 = e[lane + 32];
    float l0 = e[64 + lane];
    float l1 = e[96 + lane];
    float me = m0 * m0 + m1 * m1;            // ||mu_e||^2 partial
    float le = 0.5f * (l0 + l1);             // sum(log sigma_e) partial
    float dn = 2.0f * (expf(l0) + expf(l1)); // denominator partial
#pragma unroll
    for (int s = 16; s; s >>= 1) {
        me += __shfl_xor_sync(0xffffffffu, me, s);
        le += __shfl_xor_sync(0xffffffffu, le, s);
        dn += __shfl_xor_sync(0xffffffffu, dn, s);
    }
    float invden = 1.0f / dn;
    if (lane == 0) {
        g_A[k] = le + me * invden;
        g_invden[k] = invden;
    }
    float c = -2.0f * invden;
    g_wT[lane * KCODES + k] = c * m0;
    g_wT[(lane + 32) * KCODES + k] = c * m1;
}

// ---------------------------------------------------------------------------
// Kernel 2: score GEMM + argmin.
// Block: 256 threads (16x16), 128 tokens x 128 codes per tile, 8x8 microtile.
// 1 byte of smem traffic per FMA -> smem crossbar (128B/cyc) matches the
// fp32 FMA pipe (128 FMA/cyc). Loops 16 code tiles covering K=2048 codes.
// Dynamic smem (~67KB) -> opt-in via cudaFuncSetAttribute.
// ---------------------------------------------------------------------------
__global__ __launch_bounds__(256, 2) void dist_argmin(const float* __restrict__ x,
                                                      float* __restrict__ idsf) {
    extern __shared__ float sm[];
    float* As    = sm;                   // [h=64][token=128]
    float* Bs    = As + 64 * NTOK_TILE;  // [h=64][code=128]
    float* Ssh   = Bs + 64 * KTILE;      // [128] per-token S
    float* Atile = Ssh + NTOK_TILE;      // [128]
    float* IVt   = Atile + KTILE;        // [128]
    float* Part  = IVt + KTILE;          // [128*4] deterministic partials

    const int tid = threadIdx.x;
    const int tx = tid & 15;
    const int ty = tid >> 4;
    const int lane = tid & 31;
    const int tok0 = blockIdx.x * NTOK_TILE;

    // Load x tile (coalesced) + deterministic S reduction.
    // Each warp-iteration covers 32 consecutive features of one token.
#pragma unroll 4
    for (int j = 0; j < 64; ++j) {
        int idx = tid + j * 256;
        int t = idx >> 7;       // token within tile (0..127)
        int c = idx & 127;      // feature
        float v = x[(size_t)(tok0 + t) * D + c];
        float term;
        if (c < 64) {
            As[c * NTOK_TILE + t] = v;   // transposed store for the GEMM
            term = v * v;
        } else {
            term = expf(v);              // sigma_i^2
        }
#pragma unroll
        for (int s = 16; s; s >>= 1)
            term += __shfl_xor_sync(0xffffffffu, term, s);
        if (lane == 0) Part[t * 4 + (c >> 5)] = term;
    }
    __syncthreads();
    if (tid < NTOK_TILE)
        Ssh[tid] = Part[tid * 4] + Part[tid * 4 + 1] + Part[tid * 4 + 2] + Part[tid * 4 + 3];

    float bestv[8];
    int besti[8];
#pragma unroll
    for (int i = 0; i < 8; ++i) { bestv[i] = 3.4e38f; besti[i] = 0; }

    for (int kt = 0; kt < KCODES / KTILE; ++kt) {
        __syncthreads();  // prev Bs consumed; Ssh visible on kt=0
        // Load 64x128 code tile as float4 (coalesced along k): 8 float4/thread
#pragma unroll
        for (int it = 0; it < 8; ++it) {
            int idx4 = tid + it * 256;      // 0..2047
            int h = idx4 >> 5;              // 32 float4 per row
            int kc4 = idx4 & 31;
            float4 v = *reinterpret_cast<const float4*>(
                &g_wT[h * KCODES + kt * KTILE + kc4 * 4]);
            *reinterpret_cast<float4*>(&Bs[h * KTILE + kc4 * 4]) = v;
        }
        if (tid < KTILE) {
            Atile[tid] = g_A[kt * KTILE + tid];
            IVt[tid] = g_invden[kt * KTILE + tid];
        }
        __syncthreads();

        float acc[8][8];
#pragma unroll
        for (int i = 0; i < 8; ++i)
#pragma unroll
            for (int j = 0; j < 8; ++j) acc[i][j] = 0.0f;

#pragma unroll 8
        for (int kk = 0; kk < 64; ++kk) {
            float4 a0 = *reinterpret_cast<const float4*>(&As[kk * NTOK_TILE + ty * 8]);
            float4 a1 = *reinterpret_cast<const float4*>(&As[kk * NTOK_TILE + ty * 8 + 4]);
            float4 b0 = *reinterpret_cast<const float4*>(&Bs[kk * KTILE + tx * 8]);
            float4 b1 = *reinterpret_cast<const float4*>(&Bs[kk * KTILE + tx * 8 + 4]);
            float av[8] = {a0.x, a0.y, a0.z, a0.w, a1.x, a1.y, a1.z, a1.w};
            float bv[8] = {b0.x, b0.y, b0.z, b0.w, b1.x, b1.y, b1.z, b1.w};
#pragma unroll
            for (int i = 0; i < 8; ++i)
#pragma unroll
                for (int j = 0; j < 8; ++j)
                    acc[i][j] = fmaf(av[i], bv[j], acc[i][j]);
        }

        // Bias + running argmin (codes ascend per thread and per tile ->
        // strict < preserves jnp.argmin first-occurrence semantics)
#pragma unroll
        for (int i = 0; i < 8; ++i) {
            float S = Ssh[ty * 8 + i];
#pragma unroll
            for (int j = 0; j < 8; ++j) {
                int kc = kt * KTILE + tx * 8 + j;
                float sc = Atile[tx * 8 + j] + S * IVt[tx * 8 + j] + acc[i][j];
                if (sc < bestv[i]) { bestv[i] = sc; besti[i] = kc; }
            }
        }
    }

    // Reduce argmin across the 16 tx-threads of each token (16-lane-aligned
    // group within one warp).
#pragma unroll
    for (int i = 0; i < 8; ++i) {
        float v = bestv[i];
        int bi = besti[i];
#pragma unroll
        for (int s = 1; s < 16; s <<= 1) {
            float ov = __shfl_xor_sync(0xffffffffu, v, s);
            int oi = __shfl_xor_sync(0xffffffffu, bi, s);
            if (ov < v || (ov == v && oi < bi)) { v = ov; bi = oi; }
        }
        if (tx == 0) idsf[tok0 + ty * 8 + i] = (float)bi;
    }
}

// ---------------------------------------------------------------------------
// Kernel 3: epilogue. One warp per token.
// ---------------------------------------------------------------------------
__global__ void epilogue(const float* __restrict__ x, const float* __restrict__ emb,
                         const float* __restrict__ z, const float* __restrict__ idsf,
                         float* __restrict__ out, float* __restrict__ comm,
                         float* __restrict__ cdbk, int ntok) {
    int t = (blockIdx.x * blockDim.x + threadIdx.x) >> 5;
    int lane = threadIdx.x & 31;
    if (t >= ntok) return;
    int id = (int)idsf[t];
    const float* e = emb + (size_t)id * D;
    const float* xr = x + (size_t)t * D;
    float s = 0.0f;
#pragma unroll
    for (int c = lane; c < D; c += 32) {
        float d = e[c] - xr[c];
        s = fmaf(d, d, s);
    }
#pragma unroll
    for (int sh = 16; sh; sh >>= 1) s += __shfl_xor_sync(0xffffffffu, s, sh);
#pragma unroll
    for (int h = lane; h < H; h += 32)
        out[(size_t)t * H + h] = e[h] + expf(0.5f * e[64 + h]) * z[(size_t)t * H + h];
    if (lane == 0) {
        float m = s * (1.0f / D);
        comm[t] = m;
        cdbk[t] = m;
    }
}

// ---------------------------------------------------------------------------
extern "C" void kernel_launch(void* const* d_in, const int* in_sizes, int n_in,
                              void* d_out, int out_size) {
    // Identify inputs by element count: x (largest), emb_w (K*D), z.
    const float* x = nullptr;
    const float* emb = nullptr;
    const float* z = nullptr;
    int x_elems = 0;
    int emb_idx = -1;
    for (int i = 0; i < n_in; ++i)
        if (in_sizes[i] == KCODES * D) { emb_idx = i; break; }
    if (emb_idx < 0) emb_idx = 1;
    emb = (const float*)d_in[emb_idx];
    int a = -1, b = -1;
    for (int i = 0; i < n_in; ++i) {
        if (i == emb_idx) continue;
        if (a < 0) a = i; else b = i;
    }
    if (in_sizes[a] >= in_sizes[b]) {
        x = (const float*)d_in[a]; x_elems = in_sizes[a];
        z = (const float*)d_in[b];
    } else {
        x = (const float*)d_in[b]; x_elems = in_sizes[b];
        z = (const float*)d_in[a];
    }

    int ntok = x_elems / D;  // B*T = 32768

    float* o = (float*)d_out;
    float* outp = o;                          // (ntok, H)
    float* idsf = o + (size_t)ntok * H;       // (ntok,)
    float* comm = idsf + ntok;                // (ntok,)
    float* cdbk = comm + ntok;                // (ntok,)

    const int smem_bytes = (64 * NTOK_TILE + 64 * KTILE + NTOK_TILE + KTILE * 2 +
                            NTOK_TILE * 4) * (int)sizeof(float);
    cudaFuncSetAttribute(dist_argmin, cudaFuncAttributeMaxDynamicSharedMemorySize,
                         smem_bytes);

    prep_codes<<<KCODES / 4, 128>>>(emb);
    dist_argmin<<<ntok / NTOK_TILE, 256, smem_bytes>>>(x, idsf);
    epilogue<<<ntok / 8, 256>>>(x, emb, z, idsf, outp, comm, cdbk, ntok);
}